// round 10
// baseline (speedup 1.0000x reference)
#include <cuda_runtime.h>
#include <cuda_fp16.h>
#include <math_constants.h>

#define B_   2
#define S_   2048
#define E_   1024
#define H_   16
#define D_   64
#define M_   (B_ * S_)   // 4096
#define QSCALE_ 0.04508422f  // (1/sqrt(1024)) * log2(e)

// ---------------------------------------------------------------------------
// Scratch (static device globals; allocation is forbidden)
// ---------------------------------------------------------------------------
__device__ __half h_xq[M_ * E_];
__device__ __half h_xk[M_ * E_];
__device__ __half h_xv[M_ * E_];
__device__ __half h_wq[E_ * E_];
__device__ __half h_wk[E_ * E_];
__device__ __half h_wv[E_ * E_];
__device__ __half h_wo[E_ * E_];
__device__ __half g_Qh[B_ * H_ * S_ * D_];   // [B,H,S,D], pre-scaled by QSCALE_
__device__ __half g_Kh[B_ * H_ * S_ * D_];   // [B,H,S,D]
__device__ __half g_Vth[B_ * H_ * D_ * S_];  // [B,H,D,S] (transposed)
__device__ __half g_atth[M_ * E_];           // [B,S,E]
__device__ unsigned g_mbits[S_ * S_ / 32];   // bit-packed mask

// ---------------------------------------------------------------------------
// Pre-pass kernels
// ---------------------------------------------------------------------------
__global__ void f2h3_kernel(const float* __restrict__ s0, const float* __restrict__ s1,
                            const float* __restrict__ s2,
                            __half* __restrict__ d0, __half* __restrict__ d1,
                            __half* __restrict__ d2)
{
    int z = blockIdx.z;
    const float* s = (z == 0) ? s0 : (z == 1) ? s1 : s2;
    __half* d = (z == 0) ? d0 : (z == 1) ? d1 : d2;
    int i = blockIdx.x * 256 + threadIdx.x;
    float4 v = ((const float4*)s)[i];
    __half2* o = (__half2*)d;
    o[2 * i]     = __floats2half2_rn(v.x, v.y);
    o[2 * i + 1] = __floats2half2_rn(v.z, v.w);
}

__global__ void f2h4_kernel(const float* __restrict__ s0, const float* __restrict__ s1,
                            const float* __restrict__ s2, const float* __restrict__ s3,
                            __half* __restrict__ d0, __half* __restrict__ d1,
                            __half* __restrict__ d2, __half* __restrict__ d3)
{
    int z = blockIdx.z;
    const float* s = (z == 0) ? s0 : (z == 1) ? s1 : (z == 2) ? s2 : s3;
    __half* d = (z == 0) ? d0 : (z == 1) ? d1 : (z == 2) ? d2 : d3;
    int i = blockIdx.x * 256 + threadIdx.x;
    float4 v = ((const float4*)s)[i];
    __half2* o = (__half2*)d;
    o[2 * i]     = __floats2half2_rn(v.x, v.y);
    o[2 * i + 1] = __floats2half2_rn(v.z, v.w);
}

__global__ void maskpack_kernel(const int* __restrict__ m, unsigned* __restrict__ bits)
{
    int i = blockIdx.x * 256 + threadIdx.x;
    unsigned w = __ballot_sync(0xffffffffu, m[i] != 0);
    if ((threadIdx.x & 31) == 0) bits[i >> 5] = w;
}

// ---------------------------------------------------------------------------
// mma + ldmatrix helpers
// ---------------------------------------------------------------------------
__device__ __forceinline__ void mma_f16(float c[4], const unsigned a[4],
                                        unsigned b0, unsigned b1)
{
    asm volatile(
        "mma.sync.aligned.m16n8k16.row.col.f32.f16.f16.f32 "
        "{%0,%1,%2,%3},{%4,%5,%6,%7},{%8,%9},{%0,%1,%2,%3};"
        : "+f"(c[0]), "+f"(c[1]), "+f"(c[2]), "+f"(c[3])
        : "r"(a[0]), "r"(a[1]), "r"(a[2]), "r"(a[3]), "r"(b0), "r"(b1));
}

__device__ __forceinline__ void ldsm4(unsigned& r0, unsigned& r1,
                                      unsigned& r2, unsigned& r3, unsigned a)
{
    asm volatile("ldmatrix.sync.aligned.m8n8.x4.shared.b16 {%0,%1,%2,%3}, [%4];"
                 : "=r"(r0), "=r"(r1), "=r"(r2), "=r"(r3) : "r"(a));
}

// ---------------------------------------------------------------------------
// HGEMM: C = A[M,K] @ W[N,K]^T. 128x128 block, kTile 64, cp.async 3-stage
// pipeline, 8 warps (2m x 4n). Fragment feeds via ldmatrix.x4.
// MODE 0 (fused QKV, blockIdx.z): z=0 -> Q*[QSCALE_] to [B,H,S,D];
//   z=1 -> K to [B,H,S,D]; z=2 -> V to [B,H,D,S] via smem-staged transpose.
// MODE 1: fp32 row-major + bias.
// ---------------------------------------------------------------------------
#define HST 9216            // halves per matrix per stage (128*72)
#define GSTAGE_B (2 * HST * 2)   // bytes per stage (A+B)

__device__ __forceinline__ void hg_cp(unsigned dst, const __half* src, int tid, int ldk)
{
#pragma unroll
    for (int p = 0; p < 4; p++) {
        int i = tid + p * 256;
        int row = i >> 3, c = i & 7;
        asm volatile("cp.async.cg.shared.global [%0], [%1], 16;" ::
                     "r"(dst + (unsigned)(row * 144 + c * 16)),
                     "l"(src + (size_t)row * ldk + c * 8));
    }
}

template <int MODE>
__global__ __launch_bounds__(256, 2)
void hgemm(const __half* __restrict__ A0, const __half* __restrict__ A1,
           const __half* __restrict__ A2,
           const __half* __restrict__ W0, const __half* __restrict__ W1,
           const __half* __restrict__ W2,
           __half* __restrict__ H0, __half* __restrict__ H1, __half* __restrict__ H2,
           const float* __restrict__ bias, float* __restrict__ Cf)
{
    extern __shared__ __half sm[];
    const int tid = threadIdx.x, lane = tid & 31, warp = tid >> 5;
    const int wm = warp >> 2, wn = warp & 3;
    const int g = lane >> 2, t = lane & 3;
    const int m0 = blockIdx.y * 128, n0 = blockIdx.x * 128;
    const int z = blockIdx.z;

    const __half* A = (MODE == 1) ? A0 : (z == 0 ? A0 : z == 1 ? A1 : A2);
    const __half* W = (MODE == 1) ? W0 : (z == 0 ? W0 : z == 1 ? W1 : W2);
    const int K = E_;

    const __half* Ag = A + (size_t)m0 * K;
    const __half* Wg = W + (size_t)n0 * K;
    unsigned sbase = (unsigned)__cvta_generic_to_shared(sm);

    // per-thread ldmatrix lane offsets (bytes)
    const unsigned aoff = (unsigned)(((lane & 15) * 72 + (lane >> 4) * 8) * 2);
    const unsigned boff = (unsigned)(((((lane >> 4) & 1) * 8 + (lane & 7)) * 72 +
                                      ((lane >> 3) & 1) * 8) * 2);

    float acc[4][4][4];
#pragma unroll
    for (int mi = 0; mi < 4; mi++)
#pragma unroll
        for (int ni = 0; ni < 4; ni++)
#pragma unroll
            for (int c = 0; c < 4; c++) acc[mi][ni][c] = 0.f;

    const int NKT = K / 64;   // 16
    // Prologue: prefetch tiles 0 and 1
    hg_cp(sbase, Ag, tid, K);
    hg_cp(sbase + HST * 2, Wg, tid, K);
    asm volatile("cp.async.commit_group;");
    hg_cp(sbase + GSTAGE_B, Ag + 64, tid, K);
    hg_cp(sbase + GSTAGE_B + HST * 2, Wg + 64, tid, K);
    asm volatile("cp.async.commit_group;");

    int stage = 0, pstage = 2;
    for (int kt = 0; kt < NKT; kt++) {
        if (kt + 1 < NKT) asm volatile("cp.async.wait_group 1;");
        else              asm volatile("cp.async.wait_group 0;");
        __syncthreads();
        if (kt + 2 < NKT) {
            unsigned ps = sbase + pstage * GSTAGE_B;
            hg_cp(ps, Ag + (kt + 2) * 64, tid, K);
            hg_cp(ps + HST * 2, Wg + (kt + 2) * 64, tid, K);
            asm volatile("cp.async.commit_group;");
        }
        const unsigned sAc = sbase + stage * GSTAGE_B;
        const unsigned sBc = sAc + HST * 2;
#pragma unroll
        for (int kk = 0; kk < 64; kk += 16) {
            unsigned a[4][4], bbf[4][2];
#pragma unroll
            for (int mi = 0; mi < 4; mi++)
                ldsm4(a[mi][0], a[mi][1], a[mi][2], a[mi][3],
                      sAc + aoff + (unsigned)((((wm * 64 + mi * 16) * 72) + kk) * 2));
#pragma unroll
            for (int j = 0; j < 2; j++)
                ldsm4(bbf[2 * j][0], bbf[2 * j][1], bbf[2 * j + 1][0], bbf[2 * j + 1][1],
                      sBc + boff + (unsigned)((((wn * 32 + j * 16) * 72) + kk) * 2));
#pragma unroll
            for (int mi = 0; mi < 4; mi++)
#pragma unroll
                for (int ni = 0; ni < 4; ni++)
                    mma_f16(acc[mi][ni], a[mi], bbf[ni][0], bbf[ni][1]);
        }
        stage = (stage + 1 == 3) ? 0 : stage + 1;
        pstage = (pstage + 1 == 3) ? 0 : pstage + 1;
    }

    // ---------------- Epilogue ----------------
    if (MODE == 1) {
#pragma unroll
        for (int mi = 0; mi < 4; mi++) {
            int r0 = m0 + wm * 64 + mi * 16 + g;
            int r1 = r0 + 8;
#pragma unroll
            for (int ni = 0; ni < 4; ni++) {
                int c = n0 + wn * 32 + ni * 8 + 2 * t;
                float2 bv = *(const float2*)&bias[c];
                *(float2*)&Cf[(size_t)r0 * E_ + c] =
                    make_float2(acc[mi][ni][0] + bv.x, acc[mi][ni][1] + bv.y);
                *(float2*)&Cf[(size_t)r1 * E_ + c] =
                    make_float2(acc[mi][ni][2] + bv.x, acc[mi][ni][3] + bv.y);
            }
        }
        return;
    }

    __half* Hc = (z == 0) ? H0 : (z == 1) ? H1 : H2;
    if (z == 2) {
        // Stage transposed tile in smem, then coalesced writes to [B,H,D,S].
        __syncthreads();
        __half* stg = sm;  // 128 x 136 halves
#pragma unroll
        for (int mi = 0; mi < 4; mi++) {
            int ml = wm * 64 + mi * 16 + g;
#pragma unroll
            for (int ni = 0; ni < 4; ni++) {
                int nl = wn * 32 + ni * 8 + 2 * t;
                stg[nl * 136 + ml]           = __float2half(acc[mi][ni][0]);
                stg[(nl + 1) * 136 + ml]     = __float2half(acc[mi][ni][1]);
                stg[nl * 136 + ml + 8]       = __float2half(acc[mi][ni][2]);
                stg[(nl + 1) * 136 + ml + 8] = __float2half(acc[mi][ni][3]);
            }
        }
        __syncthreads();
        int bb = m0 >> 11, s0r = m0 & (S_ - 1);
#pragma unroll
        for (int p = 0; p < 8; p++) {
            int i = tid + p * 256;
            int r = i >> 4, cch = i & 15;
            int dg = n0 + r, hh = dg >> 6, dl = dg & 63;
            float4 v = *(const float4*)&stg[r * 136 + cch * 8];
            *(float4*)&Hc[(((size_t)(bb * H_ + hh)) * D_ + dl) * S_ + s0r + cch * 8] = v;
        }
        return;
    }

    const float qs = (z == 0) ? QSCALE_ : 1.f;
#pragma unroll
    for (int mi = 0; mi < 4; mi++) {
        int r0 = m0 + wm * 64 + mi * 16 + g;
        int r1 = r0 + 8;
#pragma unroll
        for (int ni = 0; ni < 4; ni++) {
            int c = n0 + wn * 32 + ni * 8 + 2 * t;
            int hh = c >> 6, d = c & 63;
            int b0r = r0 >> 11, s0r = r0 & (S_ - 1);
            int b1r = r1 >> 11, s1r = r1 & (S_ - 1);
            *(__half2*)&Hc[(((size_t)(b0r * H_ + hh)) * S_ + s0r) * D_ + d] =
                __floats2half2_rn(acc[mi][ni][0] * qs, acc[mi][ni][1] * qs);
            *(__half2*)&Hc[(((size_t)(b1r * H_ + hh)) * S_ + s1r) * D_ + d] =
                __floats2half2_rn(acc[mi][ni][2] * qs, acc[mi][ni][3] * qs);
        }
    }
}

// ---------------------------------------------------------------------------
// Attention: fp16 mma, max-free softmax, f16x2 exp2 (Q pre-scaled), row-sum
// via constant-ones B fragment mma. ldmatrix.x4 feeds; 3-stage cp.async
// pipeline on K/V. Block = 256 thr (8 warps), 128 queries/block, 64-key tiles.
// ---------------------------------------------------------------------------
#define ASTAGE_B (2 * 9216)   // bytes per stage (K 9216 + V 9216)

__global__ __launch_bounds__(256, 2)
void attn_h(const unsigned* __restrict__ mbits, __half* __restrict__ Oa)
{
    extern __shared__ __half asm_[];

    const int tid = threadIdx.x, lane = tid & 31, w = tid >> 5;
    const int g = lane >> 2, t = lane & 3;
    const int h = blockIdx.y, b = blockIdx.z;
    const int q0 = blockIdx.x * 128 + w * 16;

    const __half* Qb  = g_Qh  + ((size_t)(b * H_ + h) * S_ + q0) * D_;
    const __half* Kb  = g_Kh  + (size_t)(b * H_ + h) * S_ * D_;
    const __half* Vtb = g_Vth + (size_t)(b * H_ + h) * D_ * S_;

    // Persistent Q fragments (already scaled by QSCALE_)
    unsigned aq[4][4];
#pragma unroll
    for (int ks = 0; ks < 4; ks++) {
        const __half* qp = Qb + g * D_ + ks * 16 + 2 * t;
        aq[ks][0] = *(const unsigned*)qp;
        aq[ks][1] = *(const unsigned*)(qp + 8 * D_);
        aq[ks][2] = *(const unsigned*)(qp + 8);
        aq[ks][3] = *(const unsigned*)(qp + 8 * D_ + 8);
    }

    float o[8][4];
#pragma unroll
    for (int ni = 0; ni < 8; ni++)
#pragma unroll
        for (int c = 0; c < 4; c++) o[ni][c] = 0.f;
    float lacc[4] = {0.f, 0.f, 0.f, 0.f};

    unsigned sbase = (unsigned)__cvta_generic_to_shared(asm_);
    const unsigned loff = (unsigned)(((lane & 7) * 72 + (lane >> 3) * 8) * 2);
    const unsigned ONE2 = 0x3C003C00u;   // half2(1.0, 1.0)

    auto load_tile = [&](int kt, int st) {
        unsigned sKd = sbase + st * ASTAGE_B;
        unsigned sVd = sKd + 9216;
#pragma unroll
        for (int p = 0; p < 2; p++) {
            int i = tid + p * 256;
            int row = i >> 3, c = i & 7;
            asm volatile("cp.async.cg.shared.global [%0], [%1], 16;" ::
                         "r"(sKd + (unsigned)(row * 144 + c * 16)),
                         "l"(Kb + (size_t)(kt * 64 + row) * D_ + c * 8));
            asm volatile("cp.async.cg.shared.global [%0], [%1], 16;" ::
                         "r"(sVd + (unsigned)(row * 144 + c * 16)),
                         "l"(Vtb + (size_t)row * S_ + kt * 64 + c * 8));
        }
    };

    const int NT = S_ / 64;   // 32
    load_tile(0, 0);
    asm volatile("cp.async.commit_group;");
    load_tile(1, 1);
    asm volatile("cp.async.commit_group;");

    int stage = 0, pstage = 2;
    for (int kt = 0; kt < NT; kt++) {
        if (kt + 1 < NT) asm volatile("cp.async.wait_group 1;");
        else             asm volatile("cp.async.wait_group 0;");
        __syncthreads();
        if (kt + 2 < NT) {
            load_tile(kt + 2, pstage);
            asm volatile("cp.async.commit_group;");
        }
        const unsigned sKc = sbase + stage * ASTAGE_B;
        const unsigned sVc = sKc + 9216;

        // scores: 16 rows x 64 keys per warp (exp2 domain)
        float sc[8][4];
#pragma unroll
        for (int ni = 0; ni < 8; ni++)
#pragma unroll
            for (int c = 0; c < 4; c++) sc[ni][c] = 0.f;
#pragma unroll
        for (int ni = 0; ni < 8; ni++) {
            unsigned k0, k1, k2, k3;
            ldsm4(k0, k1, k2, k3, sKc + loff + (unsigned)(ni * 8 * 72 * 2));
            mma_f16(sc[ni], aq[0], k0, k1);
            mma_f16(sc[ni], aq[1], k2, k3);
            ldsm4(k0, k1, k2, k3, sKc + loff + (unsigned)((ni * 8 * 72 + 32) * 2));
            mma_f16(sc[ni], aq[2], k0, k1);
            mma_f16(sc[ni], aq[3], k2, k3);
        }

        // mask + exp2 (f16x2); pe[] is directly the PV A-fragment set
        unsigned mw0 = mbits[(q0 + g) * 64 + 2 * kt];
        unsigned mw1 = mbits[(q0 + g) * 64 + 2 * kt + 1];
        unsigned mw2 = mbits[(q0 + 8 + g) * 64 + 2 * kt];
        unsigned mw3 = mbits[(q0 + 8 + g) * 64 + 2 * kt + 1];
        unsigned pe[16];
#pragma unroll
        for (int ni = 0; ni < 8; ni++) {
            int sh = (ni * 8 + 2 * t) & 31;
            unsigned wl0 = (ni < 4) ? mw0 : mw1;
            unsigned wl1 = (ni < 4) ? mw2 : mw3;
            float v0 = ((wl0 >> sh) & 1)       ? sc[ni][0] : -100.f;
            float v1 = ((wl0 >> (sh + 1)) & 1) ? sc[ni][1] : -100.f;
            float v2 = ((wl1 >> sh) & 1)       ? sc[ni][2] : -100.f;
            float v3 = ((wl1 >> (sh + 1)) & 1) ? sc[ni][3] : -100.f;
            __half2 e0 = h2exp2(__floats2half2_rn(v0, v1));
            __half2 e1 = h2exp2(__floats2half2_rn(v2, v3));
            int idx = (ni >> 1) * 4 + (ni & 1) * 2;
            pe[idx]     = *(unsigned*)&e0;
            pe[idx + 1] = *(unsigned*)&e1;
        }

        // O += P @ V
#pragma unroll
        for (int ni = 0; ni < 8; ni++) {
            unsigned v0, v1, v2, v3;
            ldsm4(v0, v1, v2, v3, sVc + loff + (unsigned)(ni * 8 * 72 * 2));
            mma_f16(o[ni], &pe[0], v0, v1);
            mma_f16(o[ni], &pe[4], v2, v3);
            ldsm4(v0, v1, v2, v3, sVc + loff + (unsigned)((ni * 8 * 72 + 32) * 2));
            mma_f16(o[ni], &pe[8],  v0, v1);
            mma_f16(o[ni], &pe[12], v2, v3);
        }
        // l += P @ ones (constant B fragment, no memory)
#pragma unroll
        for (int ks = 0; ks < 4; ks++)
            mma_f16(lacc, &pe[ks * 4], ONE2, ONE2);

        stage = (stage + 1 == 3) ? 0 : stage + 1;
        pstage = (pstage + 1 == 3) ? 0 : pstage + 1;
    }

    float li0 = 1.f / lacc[0], li1 = 1.f / lacc[2];
    __half* o0p = Oa + ((size_t)b * S_ + q0 + g) * E_ + h * D_;
    __half* o1p = Oa + ((size_t)b * S_ + q0 + 8 + g) * E_ + h * D_;
#pragma unroll
    for (int ni = 0; ni < 8; ni++) {
        *(__half2*)(o0p + ni * 8 + 2 * t) =
            __floats2half2_rn(o[ni][0] * li0, o[ni][1] * li0);
        *(__half2*)(o1p + ni * 8 + 2 * t) =
            __floats2half2_rn(o[ni][2] * li1, o[ni][3] * li1);
    }
}

// ---------------------------------------------------------------------------
extern "C" void kernel_launch(void* const* d_in, const int* in_sizes, int n_in,
                              void* d_out, int out_size)
{
    const float* query  = (const float*)d_in[0];
    const float* keys   = (const float*)d_in[1];
    const float* values = (const float*)d_in[2];
    const int*   mask   = (const int*)  d_in[3];
    const float* Wq     = (const float*)d_in[4];
    const float* Wk     = (const float*)d_in[5];
    const float* Wv     = (const float*)d_in[6];
    const float* Wo     = (const float*)d_in[7];
    const float* bo     = (const float*)d_in[8];
    float* out = (float*)d_out;

    void *pxq, *pxk, *pxv, *pwq, *pwk, *pwv, *pwo, *pQ, *pK, *pVt, *pA, *pMB;
    cudaGetSymbolAddress(&pxq, h_xq);  cudaGetSymbolAddress(&pxk, h_xk);
    cudaGetSymbolAddress(&pxv, h_xv);  cudaGetSymbolAddress(&pwq, h_wq);
    cudaGetSymbolAddress(&pwk, h_wk);  cudaGetSymbolAddress(&pwv, h_wv);
    cudaGetSymbolAddress(&pwo, h_wo);  cudaGetSymbolAddress(&pQ,  g_Qh);
    cudaGetSymbolAddress(&pK,  g_Kh);  cudaGetSymbolAddress(&pVt, g_Vth);
    cudaGetSymbolAddress(&pA,  g_atth);
    cudaGetSymbolAddress(&pMB, g_mbits);

    const int nin4 = M_ * E_ / 4;   // 1M float4
    const int nw4  = E_ * E_ / 4;   // 256K float4
    f2h3_kernel<<<dim3(nin4 / 256, 1, 3), 256>>>(
        query, keys, values, (__half*)pxq, (__half*)pxk, (__half*)pxv);
    f2h4_kernel<<<dim3(nw4 / 256, 1, 4), 256>>>(
        Wq, Wk, Wv, Wo, (__half*)pwq, (__half*)pwk, (__half*)pwv, (__half*)pwo);
    maskpack_kernel<<<(S_ * S_) / 256, 256>>>(mask, (unsigned*)pMB);

    const int gsmem = 3 * GSTAGE_B;   // 110592 bytes
    cudaFuncSetAttribute(hgemm<0>, cudaFuncAttributeMaxDynamicSharedMemorySize, gsmem);
    cudaFuncSetAttribute(hgemm<1>, cudaFuncAttributeMaxDynamicSharedMemorySize, gsmem);
    const int asmem = 3 * ASTAGE_B;   // 110592 bytes
    cudaFuncSetAttribute(attn_h, cudaFuncAttributeMaxDynamicSharedMemorySize, asmem);

    // Fused Q/K/V projections (Q pre-scaled, V transposed)
    hgemm<0><<<dim3(8, 32, 3), 256, gsmem>>>(
        (const __half*)pxq, (const __half*)pxk, (const __half*)pxv,
        (const __half*)pwq, (const __half*)pwk, (const __half*)pwv,
        (__half*)pQ, (__half*)pK, (__half*)pVt, nullptr, nullptr);

    attn_h<<<dim3(S_ / 128, H_, B_), 256, asmem>>>((const unsigned*)pMB, (__half*)pA);

    // Output projection (fp32 + bias)
    hgemm<1><<<dim3(8, 32, 1), 256, gsmem>>>(
        (const __half*)pA, nullptr, nullptr,
        (const __half*)pwo, nullptr, nullptr,
        nullptr, nullptr, nullptr, bo, out);
}

// round 13
// speedup vs baseline: 1.0346x; 1.0346x over previous
#include <cuda_runtime.h>
#include <cuda_fp16.h>
#include <math_constants.h>

#define B_   2
#define S_   2048
#define E_   1024
#define H_   16
#define D_   64
#define M_   (B_ * S_)   // 4096
#define QSCALE_ 0.04508422f  // (1/sqrt(1024)) * log2(e)

// ---------------------------------------------------------------------------
// Scratch (static device globals; allocation is forbidden)
// ---------------------------------------------------------------------------
__device__ __half h_xq[M_ * E_];
__device__ __half h_xk[M_ * E_];
__device__ __half h_xv[M_ * E_];
__device__ __half h_wq[E_ * E_];
__device__ __half h_wk[E_ * E_];
__device__ __half h_wv[E_ * E_];
__device__ __half h_wo[E_ * E_];
__device__ __half g_Qh[B_ * H_ * S_ * D_];   // [B,H,S,D], pre-scaled by QSCALE_
__device__ __half g_Kh[B_ * H_ * S_ * D_];   // [B,H,S,D]
__device__ __half g_Vth[B_ * H_ * D_ * S_];  // [B,H,D,S] (transposed)
__device__ __half g_atth[M_ * E_];           // [B,S,E]
__device__ unsigned g_mbits[S_ * S_ / 32];   // bit-packed mask

// ---------------------------------------------------------------------------
// Pre-pass kernels: one fused f2h over 7 tensors (3 inputs + 4 weights)
// ---------------------------------------------------------------------------
__global__ void f2h7_kernel(const float* __restrict__ s0, const float* __restrict__ s1,
                            const float* __restrict__ s2, const float* __restrict__ s3,
                            const float* __restrict__ s4, const float* __restrict__ s5,
                            const float* __restrict__ s6,
                            __half* __restrict__ d0, __half* __restrict__ d1,
                            __half* __restrict__ d2, __half* __restrict__ d3,
                            __half* __restrict__ d4, __half* __restrict__ d5,
                            __half* __restrict__ d6)
{
    int z = blockIdx.z;
    const float* s; __half* d; int n4;
    switch (z) {
        case 0: s = s0; d = d0; n4 = M_ * E_ / 4; break;
        case 1: s = s1; d = d1; n4 = M_ * E_ / 4; break;
        case 2: s = s2; d = d2; n4 = M_ * E_ / 4; break;
        case 3: s = s3; d = d3; n4 = E_ * E_ / 4; break;
        case 4: s = s4; d = d4; n4 = E_ * E_ / 4; break;
        case 5: s = s5; d = d5; n4 = E_ * E_ / 4; break;
        default: s = s6; d = d6; n4 = E_ * E_ / 4; break;
    }
    int i = blockIdx.x * 256 + threadIdx.x;
    if (i < n4) {
        float4 v = ((const float4*)s)[i];
        __half2* o = (__half2*)d;
        o[2 * i]     = __floats2half2_rn(v.x, v.y);
        o[2 * i + 1] = __floats2half2_rn(v.z, v.w);
    }
}

__global__ void maskpack_kernel(const int* __restrict__ m, unsigned* __restrict__ bits)
{
    int i = blockIdx.x * 256 + threadIdx.x;
    unsigned w = __ballot_sync(0xffffffffu, m[i] != 0);
    if ((threadIdx.x & 31) == 0) bits[i >> 5] = w;
}

// ---------------------------------------------------------------------------
// mma + ldmatrix helpers
// ---------------------------------------------------------------------------
__device__ __forceinline__ void mma_f16(float c[4], const unsigned a[4],
                                        unsigned b0, unsigned b1)
{
    asm volatile(
        "mma.sync.aligned.m16n8k16.row.col.f32.f16.f16.f32 "
        "{%0,%1,%2,%3},{%4,%5,%6,%7},{%8,%9},{%0,%1,%2,%3};"
        : "+f"(c[0]), "+f"(c[1]), "+f"(c[2]), "+f"(c[3])
        : "r"(a[0]), "r"(a[1]), "r"(a[2]), "r"(a[3]), "r"(b0), "r"(b1));
}

__device__ __forceinline__ void ldsm4(unsigned& r0, unsigned& r1,
                                      unsigned& r2, unsigned& r3, unsigned a)
{
    asm volatile("ldmatrix.sync.aligned.m8n8.x4.shared.b16 {%0,%1,%2,%3}, [%4];"
                 : "=r"(r0), "=r"(r1), "=r"(r2), "=r"(r3) : "r"(a));
}

// ---------------------------------------------------------------------------
// HGEMM (R9-best): C = A[M,K] @ W[N,K]^T. 128x128 block, kTile 64, cp.async
// 2-stage, 8 warps (2m x 4n). Fragment feeds via ldmatrix.x4.
// MODE 0 (fused QKV, blockIdx.z): z=0 -> Q*[QSCALE_] to [B,H,S,D];
//   z=1 -> K to [B,H,S,D]; z=2 -> V to [B,H,D,S] via smem-staged transpose.
// MODE 1: fp32 row-major + bias.
// ---------------------------------------------------------------------------
#define HST 9216   // halves per stage per matrix (128*72)

__device__ __forceinline__ void hg_cp(unsigned dst, const __half* src, int tid, int ldk)
{
#pragma unroll
    for (int p = 0; p < 4; p++) {
        int i = tid + p * 256;
        int row = i >> 3, c = i & 7;
        asm volatile("cp.async.cg.shared.global [%0], [%1], 16;" ::
                     "r"(dst + (unsigned)(row * 144 + c * 16)),
                     "l"(src + (size_t)row * ldk + c * 8));
    }
}

template <int MODE>
__global__ __launch_bounds__(256, 2)
void hgemm(const __half* __restrict__ A0, const __half* __restrict__ A1,
           const __half* __restrict__ A2,
           const __half* __restrict__ W0, const __half* __restrict__ W1,
           const __half* __restrict__ W2,
           __half* __restrict__ H0, __half* __restrict__ H1, __half* __restrict__ H2,
           const float* __restrict__ bias, float* __restrict__ Cf)
{
    extern __shared__ __half sm[];
    const int tid = threadIdx.x, lane = tid & 31, warp = tid >> 5;
    const int wm = warp >> 2, wn = warp & 3;
    const int g = lane >> 2, t = lane & 3;
    const int m0 = blockIdx.y * 128, n0 = blockIdx.x * 128;
    const int z = blockIdx.z;

    const __half* A = (MODE == 1) ? A0 : (z == 0 ? A0 : z == 1 ? A1 : A2);
    const __half* W = (MODE == 1) ? W0 : (z == 0 ? W0 : z == 1 ? W1 : W2);
    const int K = E_;

    const __half* Ag = A + (size_t)m0 * K;
    const __half* Wg = W + (size_t)n0 * K;
    unsigned sA = (unsigned)__cvta_generic_to_shared(sm);
    unsigned sB = sA + 2 * HST * 2;

    // per-thread ldmatrix lane offsets (bytes)
    const unsigned aoff = (unsigned)(((lane & 15) * 72 + (lane >> 4) * 8) * 2);
    const unsigned boff = (unsigned)(((((lane >> 4) & 1) * 8 + (lane & 7)) * 72 +
                                      ((lane >> 3) & 1) * 8) * 2);

    float acc[4][4][4];
#pragma unroll
    for (int mi = 0; mi < 4; mi++)
#pragma unroll
        for (int ni = 0; ni < 4; ni++)
#pragma unroll
            for (int c = 0; c < 4; c++) acc[mi][ni][c] = 0.f;

    hg_cp(sA, Ag, tid, K);
    hg_cp(sB, Wg, tid, K);
    asm volatile("cp.async.commit_group;");

    const int NKT = K / 64;   // 16
    for (int kt = 0; kt < NKT; kt++) {
        asm volatile("cp.async.wait_group 0;");
        __syncthreads();
        if (kt + 1 < NKT) {
            int nb = (kt + 1) & 1;
            hg_cp(sA + nb * HST * 2, Ag + (kt + 1) * 64, tid, K);
            hg_cp(sB + nb * HST * 2, Wg + (kt + 1) * 64, tid, K);
            asm volatile("cp.async.commit_group;");
        }
        const unsigned sAc = sA + (kt & 1) * HST * 2;
        const unsigned sBc = sB + (kt & 1) * HST * 2;
#pragma unroll
        for (int kk = 0; kk < 64; kk += 16) {
            unsigned a[4][4], bbf[4][2];
#pragma unroll
            for (int mi = 0; mi < 4; mi++)
                ldsm4(a[mi][0], a[mi][1], a[mi][2], a[mi][3],
                      sAc + aoff + (unsigned)((((wm * 64 + mi * 16) * 72) + kk) * 2));
#pragma unroll
            for (int j = 0; j < 2; j++)
                ldsm4(bbf[2 * j][0], bbf[2 * j][1], bbf[2 * j + 1][0], bbf[2 * j + 1][1],
                      sBc + boff + (unsigned)((((wn * 32 + j * 16) * 72) + kk) * 2));
#pragma unroll
            for (int mi = 0; mi < 4; mi++)
#pragma unroll
                for (int ni = 0; ni < 4; ni++)
                    mma_f16(acc[mi][ni], a[mi], bbf[ni][0], bbf[ni][1]);
        }
    }

    // ---------------- Epilogue ----------------
    if (MODE == 1) {
#pragma unroll
        for (int mi = 0; mi < 4; mi++) {
            int r0 = m0 + wm * 64 + mi * 16 + g;
            int r1 = r0 + 8;
#pragma unroll
            for (int ni = 0; ni < 4; ni++) {
                int c = n0 + wn * 32 + ni * 8 + 2 * t;
                float2 bv = *(const float2*)&bias[c];
                *(float2*)&Cf[(size_t)r0 * E_ + c] =
                    make_float2(acc[mi][ni][0] + bv.x, acc[mi][ni][1] + bv.y);
                *(float2*)&Cf[(size_t)r1 * E_ + c] =
                    make_float2(acc[mi][ni][2] + bv.x, acc[mi][ni][3] + bv.y);
            }
        }
        return;
    }

    __half* Hc = (z == 0) ? H0 : (z == 1) ? H1 : H2;
    if (z == 2) {
        // Stage transposed tile in smem, then coalesced writes to [B,H,D,S].
        __syncthreads();
        __half* stg = sm;  // 128 x 136 halves
#pragma unroll
        for (int mi = 0; mi < 4; mi++) {
            int ml = wm * 64 + mi * 16 + g;
#pragma unroll
            for (int ni = 0; ni < 4; ni++) {
                int nl = wn * 32 + ni * 8 + 2 * t;
                stg[nl * 136 + ml]           = __float2half(acc[mi][ni][0]);
                stg[(nl + 1) * 136 + ml]     = __float2half(acc[mi][ni][1]);
                stg[nl * 136 + ml + 8]       = __float2half(acc[mi][ni][2]);
                stg[(nl + 1) * 136 + ml + 8] = __float2half(acc[mi][ni][3]);
            }
        }
        __syncthreads();
        int bb = m0 >> 11, s0r = m0 & (S_ - 1);
#pragma unroll
        for (int p = 0; p < 8; p++) {
            int i = tid + p * 256;
            int r = i >> 4, cch = i & 15;
            int dg = n0 + r, hh = dg >> 6, dl = dg & 63;
            float4 v = *(const float4*)&stg[r * 136 + cch * 8];
            *(float4*)&Hc[(((size_t)(bb * H_ + hh)) * D_ + dl) * S_ + s0r + cch * 8] = v;
        }
        return;
    }

    const float qs = (z == 0) ? QSCALE_ : 1.f;
#pragma unroll
    for (int mi = 0; mi < 4; mi++) {
        int r0 = m0 + wm * 64 + mi * 16 + g;
        int r1 = r0 + 8;
#pragma unroll
        for (int ni = 0; ni < 4; ni++) {
            int c = n0 + wn * 32 + ni * 8 + 2 * t;
            int hh = c >> 6, d = c & 63;
            int b0r = r0 >> 11, s0r = r0 & (S_ - 1);
            int b1r = r1 >> 11, s1r = r1 & (S_ - 1);
            *(__half2*)&Hc[(((size_t)(b0r * H_ + hh)) * S_ + s0r) * D_ + d] =
                __floats2half2_rn(acc[mi][ni][0] * qs, acc[mi][ni][1] * qs);
            *(__half2*)&Hc[(((size_t)(b1r * H_ + hh)) * S_ + s1r) * D_ + d] =
                __floats2half2_rn(acc[mi][ni][2] * qs, acc[mi][ni][3] * qs);
        }
    }
}

// ---------------------------------------------------------------------------
// Attention: fp16 mma, max-free softmax, f16x2 exp2, row-sum via ones-B mma,
// ldmatrix feeds. 128-key outer tiles (two 64-key inner halves) -> half the
// barriers vs 64-key tiling. 2-stage cp.async. Block = 256 thr (8 warps),
// 128 queries/block.
// Stage layout (bytes): K tile 128x64h @ stride 144 (18432B), then
// V tile 64x128h @ stride 272 (17408B). Stage stride 35840B, 2 stages.
// ---------------------------------------------------------------------------
#define A_KST   18432
#define A_STAGE 35840

__global__ __launch_bounds__(256, 2)
void attn_h(const unsigned* __restrict__ mbits, __half* __restrict__ Oa)
{
    extern __shared__ __half asmem[];

    const int tid = threadIdx.x, lane = tid & 31, w = tid >> 5;
    const int g = lane >> 2, t = lane & 3;
    const int h = blockIdx.y, b = blockIdx.z;
    const int q0 = blockIdx.x * 128 + w * 16;

    const __half* Qb  = g_Qh  + ((size_t)(b * H_ + h) * S_ + q0) * D_;
    const __half* Kb  = g_Kh  + (size_t)(b * H_ + h) * S_ * D_;
    const __half* Vtb = g_Vth + (size_t)(b * H_ + h) * D_ * S_;

    // Persistent Q fragments (already scaled by QSCALE_)
    unsigned aq[4][4];
#pragma unroll
    for (int ks = 0; ks < 4; ks++) {
        const __half* qp = Qb + g * D_ + ks * 16 + 2 * t;
        aq[ks][0] = *(const unsigned*)qp;
        aq[ks][1] = *(const unsigned*)(qp + 8 * D_);
        aq[ks][2] = *(const unsigned*)(qp + 8);
        aq[ks][3] = *(const unsigned*)(qp + 8 * D_ + 8);
    }

    float o[8][4];
#pragma unroll
    for (int ni = 0; ni < 8; ni++)
#pragma unroll
        for (int c = 0; c < 4; c++) o[ni][c] = 0.f;
    float lacc[4] = {0.f, 0.f, 0.f, 0.f};

    unsigned sb = (unsigned)__cvta_generic_to_shared(asmem);
    const unsigned loffK = (unsigned)((lane & 7) * 144 + (lane >> 3) * 16);
    const unsigned loffV = (unsigned)((lane & 7) * 272 + (lane >> 3) * 16);
    const unsigned ONE2 = 0x3C003C00u;   // half2(1.0, 1.0)

    // one 128-key tile: K 128x64h + V 64x128h (8 cp.async per thread)
    auto load_tile = [&](int kt, int buf) {
        unsigned kb = sb + buf * A_STAGE;
        unsigned vb = kb + A_KST;
#pragma unroll
        for (int p = 0; p < 4; p++) {
            int i = tid + p * 256;
            int row = i >> 3, c = i & 7;           // K: row 0..127, col-chunk 0..7
            asm volatile("cp.async.cg.shared.global [%0], [%1], 16;" ::
                         "r"(kb + (unsigned)(row * 144 + c * 16)),
                         "l"(Kb + (size_t)(kt * 128 + row) * D_ + c * 8));
        }
#pragma unroll
        for (int p = 0; p < 4; p++) {
            int i = tid + p * 256;
            int row = i >> 4, c = i & 15;          // V: row 0..63, col-chunk 0..15
            asm volatile("cp.async.cg.shared.global [%0], [%1], 16;" ::
                         "r"(vb + (unsigned)(row * 272 + c * 16)),
                         "l"(Vtb + (size_t)row * S_ + kt * 128 + c * 8));
        }
    };

    const int NT = S_ / 128;   // 16
    load_tile(0, 0);
    asm volatile("cp.async.commit_group;");

    for (int kt = 0; kt < NT; kt++) {
        asm volatile("cp.async.wait_group 0;");
        __syncthreads();
        if (kt + 1 < NT) {
            load_tile(kt + 1, (kt + 1) & 1);
            asm volatile("cp.async.commit_group;");
        }
        const unsigned sKc = sb + (kt & 1) * A_STAGE;
        const unsigned sVc = sKc + A_KST;

#pragma unroll
        for (int hf = 0; hf < 2; hf++) {
            const unsigned sKh = sKc + (unsigned)(hf * 64 * 144);
            const unsigned vco = (unsigned)(hf * 128);   // 64 keys * 2B

            // scores: 16 rows x 64 keys per warp (exp2 domain)
            float sc[8][4];
#pragma unroll
            for (int ni = 0; ni < 8; ni++)
#pragma unroll
                for (int c = 0; c < 4; c++) sc[ni][c] = 0.f;
#pragma unroll
            for (int ni = 0; ni < 8; ni++) {
                unsigned k0, k1, k2, k3;
                ldsm4(k0, k1, k2, k3, sKh + loffK + (unsigned)(ni * 8 * 144));
                mma_f16(sc[ni], aq[0], k0, k1);
                mma_f16(sc[ni], aq[1], k2, k3);
                ldsm4(k0, k1, k2, k3, sKh + loffK + (unsigned)(ni * 8 * 144 + 64));
                mma_f16(sc[ni], aq[2], k0, k1);
                mma_f16(sc[ni], aq[3], k2, k3);
            }

            // mask + exp2 (f16x2); pe[] is directly the PV A-fragment set
            int mbase = kt * 4 + hf * 2;
            unsigned mw0 = mbits[(q0 + g) * 64 + mbase];
            unsigned mw1 = mbits[(q0 + g) * 64 + mbase + 1];
            unsigned mw2 = mbits[(q0 + 8 + g) * 64 + mbase];
            unsigned mw3 = mbits[(q0 + 8 + g) * 64 + mbase + 1];
            unsigned pe[16];
#pragma unroll
            for (int ni = 0; ni < 8; ni++) {
                int sh = (ni * 8 + 2 * t) & 31;
                unsigned wl0 = (ni < 4) ? mw0 : mw1;
                unsigned wl1 = (ni < 4) ? mw2 : mw3;
                float v0 = ((wl0 >> sh) & 1)       ? sc[ni][0] : -100.f;
                float v1 = ((wl0 >> (sh + 1)) & 1) ? sc[ni][1] : -100.f;
                float v2 = ((wl1 >> sh) & 1)       ? sc[ni][2] : -100.f;
                float v3 = ((wl1 >> (sh + 1)) & 1) ? sc[ni][3] : -100.f;
                __half2 e0 = h2exp2(__floats2half2_rn(v0, v1));
                __half2 e1 = h2exp2(__floats2half2_rn(v2, v3));
                int idx = (ni >> 1) * 4 + (ni & 1) * 2;
                pe[idx]     = *(unsigned*)&e0;
                pe[idx + 1] = *(unsigned*)&e1;
            }

            // O += P @ V
#pragma unroll
            for (int ni = 0; ni < 8; ni++) {
                unsigned v0, v1, v2, v3;
                ldsm4(v0, v1, v2, v3, sVc + loffV + (unsigned)(ni * 8 * 272) + vco);
                mma_f16(o[ni], &pe[0], v0, v1);
                mma_f16(o[ni], &pe[4], v2, v3);
                ldsm4(v0, v1, v2, v3, sVc + loffV + (unsigned)(ni * 8 * 272 + 64) + vco);
                mma_f16(o[ni], &pe[8],  v0, v1);
                mma_f16(o[ni], &pe[12], v2, v3);
            }
            // l += P @ ones (constant B fragment, no memory)
#pragma unroll
            for (int ks = 0; ks < 4; ks++)
                mma_f16(lacc, &pe[ks * 4], ONE2, ONE2);
        }
    }

    float li0 = 1.f / lacc[0], li1 = 1.f / lacc[2];
    __half* o0p = Oa + ((size_t)b * S_ + q0 + g) * E_ + h * D_;
    __half* o1p = Oa + ((size_t)b * S_ + q0 + 8 + g) * E_ + h * D_;
#pragma unroll
    for (int ni = 0; ni < 8; ni++) {
        *(__half2*)(o0p + ni * 8 + 2 * t) =
            __floats2half2_rn(o[ni][0] * li0, o[ni][1] * li0);
        *(__half2*)(o1p + ni * 8 + 2 * t) =
            __floats2half2_rn(o[ni][2] * li1, o[ni][3] * li1);
    }
}

// ---------------------------------------------------------------------------
extern "C" void kernel_launch(void* const* d_in, const int* in_sizes, int n_in,
                              void* d_out, int out_size)
{
    const float* query  = (const float*)d_in[0];
    const float* keys   = (const float*)d_in[1];
    const float* values = (const float*)d_in[2];
    const int*   mask   = (const int*)  d_in[3];
    const float* Wq     = (const float*)d_in[4];
    const float* Wk     = (const float*)d_in[5];
    const float* Wv     = (const float*)d_in[6];
    const float* Wo     = (const float*)d_in[7];
    const float* bo     = (const float*)d_in[8];
    float* out = (float*)d_out;

    void *pxq, *pxk, *pxv, *pwq, *pwk, *pwv, *pwo, *pQ, *pK, *pVt, *pA, *pMB;
    cudaGetSymbolAddress(&pxq, h_xq);  cudaGetSymbolAddress(&pxk, h_xk);
    cudaGetSymbolAddress(&pxv, h_xv);  cudaGetSymbolAddress(&pwq, h_wq);
    cudaGetSymbolAddress(&pwk, h_wk);  cudaGetSymbolAddress(&pwv, h_wv);
    cudaGetSymbolAddress(&pwo, h_wo);  cudaGetSymbolAddress(&pQ,  g_Qh);
    cudaGetSymbolAddress(&pK,  g_Kh);  cudaGetSymbolAddress(&pVt, g_Vth);
    cudaGetSymbolAddress(&pA,  g_atth);
    cudaGetSymbolAddress(&pMB, g_mbits);

    const int nin4 = M_ * E_ / 4;   // 1M float4 (max slice)
    f2h7_kernel<<<dim3(nin4 / 256, 1, 7), 256>>>(
        query, keys, values, Wq, Wk, Wv, Wo,
        (__half*)pxq, (__half*)pxk, (__half*)pxv,
        (__half*)pwq, (__half*)pwk, (__half*)pwv, (__half*)pwo);
    maskpack_kernel<<<(S_ * S_) / 256, 256>>>(mask, (unsigned*)pMB);

    const int gsmem = 4 * HST * 2;   // 73728 bytes
    cudaFuncSetAttribute(hgemm<0>, cudaFuncAttributeMaxDynamicSharedMemorySize, gsmem);
    cudaFuncSetAttribute(hgemm<1>, cudaFuncAttributeMaxDynamicSharedMemorySize, gsmem);
    const int asmem = 2 * A_STAGE;   // 71680 bytes
    cudaFuncSetAttribute(attn_h, cudaFuncAttributeMaxDynamicSharedMemorySize, asmem);

    // Fused Q/K/V projections (Q pre-scaled, V transposed)
    hgemm<0><<<dim3(8, 32, 3), 256, gsmem>>>(
        (const __half*)pxq, (const __half*)pxk, (const __half*)pxv,
        (const __half*)pwq, (const __half*)pwk, (const __half*)pwv,
        (__half*)pQ, (__half*)pK, (__half*)pVt, nullptr, nullptr);

    attn_h<<<dim3(S_ / 128, H_, B_), 256, asmem>>>((const unsigned*)pMB, (__half*)pA);

    // Output projection (fp32 + bias)
    hgemm<1><<<dim3(8, 32, 1), 256, gsmem>>>(
        (const __half*)pA, nullptr, nullptr,
        (const __half*)pwo, nullptr, nullptr,
        nullptr, nullptr, nullptr, bo, out);
}